// round 1
// baseline (speedup 1.0000x reference)
#include <cuda_runtime.h>
#include <cuda_bf16.h>

// Problem dims (fixed by setup_inputs)
#define SLEN 1024
#define BSZ  32
#define INDIM 512
#define NH   8
#define HD   64
#define NTOK (SLEN*BSZ)          // 32768
#define NPROJ (NH*(3*HD+1))      // 1544
#define LN_EPS 1e-5f

// ---------------- scratch (device globals; no runtime alloc) ----------------
__device__ __align__(256) float g_h[NTOK * INDIM];      // LN output
__device__ __align__(256) float g_qkvb[NTOK * NPROJ];   // projection output
__device__ __align__(256) float g_outs[NTOK * INDIM];   // recurrence output

// ---------------- LayerNorm ----------------
__global__ __launch_bounds__(128) void ln_kernel(const float* __restrict__ x,
                                                 const float* __restrict__ gamma,
                                                 const float* __restrict__ beta,
                                                 float* __restrict__ h) {
    int row = blockIdx.x;
    int tid = threadIdx.x;
    int lane = tid & 31, wid = tid >> 5;
    const float4* xr = (const float4*)(x + (size_t)row * INDIM);
    float4 v = xr[tid];

    float s = v.x + v.y + v.z + v.w;
    #pragma unroll
    for (int o = 16; o > 0; o >>= 1) s += __shfl_xor_sync(0xffffffffu, s, o);
    __shared__ float sm[4], sm2[4];
    if (lane == 0) sm[wid] = s;
    __syncthreads();
    float mu = (sm[0] + sm[1] + sm[2] + sm[3]) * (1.0f / INDIM);

    float dx = v.x - mu, dy = v.y - mu, dz = v.z - mu, dw = v.w - mu;
    float sq = dx*dx + dy*dy + dz*dz + dw*dw;
    #pragma unroll
    for (int o = 16; o > 0; o >>= 1) sq += __shfl_xor_sync(0xffffffffu, sq, o);
    if (lane == 0) sm2[wid] = sq;
    __syncthreads();
    float var = (sm2[0] + sm2[1] + sm2[2] + sm2[3]) * (1.0f / INDIM);
    float rstd = rsqrtf(var + LN_EPS);

    float4 g = ((const float4*)gamma)[tid];
    float4 b = ((const float4*)beta)[tid];
    float4 o;
    o.x = dx * rstd * g.x + b.x;
    o.y = dy * rstd * g.y + b.y;
    o.z = dz * rstd * g.z + b.z;
    o.w = dw * rstd * g.w + b.w;
    ((float4*)(h + (size_t)row * INDIM))[tid] = o;
}

// ---------------- SGEMM 128x128x8, 256 thr, 8x8 microtile ----------------
// C[M,N] = A[M,K] @ B[K,N]  (+ RES[M,N] if RES != nullptr)
__global__ __launch_bounds__(256) void sgemm_kernel(const float* __restrict__ A,
                                                    const float* __restrict__ B,
                                                    const float* __restrict__ RES,
                                                    float* __restrict__ C,
                                                    int M, int N, int K) {
    __shared__ float As[8][128];
    __shared__ float Bs[8][128];

    int bx = blockIdx.x, by = blockIdx.y;
    int tid = threadIdx.x;

    int arow = tid >> 1;           // 0..127
    int acol = (tid & 1) << 2;     // 0 or 4
    int brow = tid >> 5;           // 0..7
    int bcol = (tid & 31) << 2;    // 0..124

    int trow = (tid >> 4) << 3;    // 0..120 (M within tile)
    int tcol = (tid & 15) << 3;    // 0..120 (N within tile)

    float acc[8][8];
    #pragma unroll
    for (int i = 0; i < 8; i++)
        #pragma unroll
        for (int j = 0; j < 8; j++) acc[i][j] = 0.0f;

    const float* Aptr = A + (size_t)(by * 128 + arow) * K + acol;
    int gcolB = bx * 128 + bcol;
    bool bvalid = (gcolB + 3) < N;   // N % 4 == 0 for our shapes

    for (int k0 = 0; k0 < K; k0 += 8) {
        float4 a4 = *(const float4*)(Aptr + k0);
        As[acol + 0][arow] = a4.x;
        As[acol + 1][arow] = a4.y;
        As[acol + 2][arow] = a4.z;
        As[acol + 3][arow] = a4.w;
        float4 b4 = make_float4(0.f, 0.f, 0.f, 0.f);
        if (bvalid) b4 = *(const float4*)(B + (size_t)(k0 + brow) * N + gcolB);
        *(float4*)&Bs[brow][bcol] = b4;
        __syncthreads();

        #pragma unroll
        for (int kk = 0; kk < 8; kk++) {
            float a[8], b[8];
            *(float4*)&a[0] = *(const float4*)&As[kk][trow];
            *(float4*)&a[4] = *(const float4*)&As[kk][trow + 4];
            *(float4*)&b[0] = *(const float4*)&Bs[kk][tcol];
            *(float4*)&b[4] = *(const float4*)&Bs[kk][tcol + 4];
            #pragma unroll
            for (int i = 0; i < 8; i++)
                #pragma unroll
                for (int j = 0; j < 8; j++)
                    acc[i][j] = fmaf(a[i], b[j], acc[i][j]);
        }
        __syncthreads();
    }

    #pragma unroll
    for (int i = 0; i < 8; i++) {
        size_t grow = (size_t)(by * 128 + trow + i);
        #pragma unroll
        for (int j = 0; j < 8; j += 4) {
            int gcol = bx * 128 + tcol + j;
            if (gcol < N) {
                float4 r;
                r.x = acc[i][j + 0];
                r.y = acc[i][j + 1];
                r.z = acc[i][j + 2];
                r.w = acc[i][j + 3];
                if (RES) {
                    float4 xr = *(const float4*)(RES + grow * N + gcol);
                    r.x += xr.x; r.y += xr.y; r.z += xr.z; r.w += xr.w;
                }
                *(float4*)(C + grow * N + gcol) = r;
            }
        }
    }
}

// ---------------- Delta-rule recurrence ----------------
// One CTA per (b, h) chain. 128 threads: r = tid&63 (W row), half = tid>>6.
// Each thread holds W[r][half*32 .. half*32+31] in registers.
// sum_norm factors folded into per-step scalars (rq, rk) so normalization is O(1).
__global__ __launch_bounds__(128) void delta_kernel(const float* __restrict__ qkvb,
                                                    float* __restrict__ outs) {
    const int bh = blockIdx.x;         // 0..255
    const int b  = bh >> 3;            // batch
    const int h  = bh & 7;             // head
    const int tid = threadIdx.x;
    const int r = tid & 63;
    const int half = tid >> 6;
    const int j0 = half << 5;
    const int lane = tid & 31;
    const int wid = tid >> 5;

    __shared__ __align__(16) float raw[2][196];
    __shared__ __align__(16) float sq[64];
    __shared__ __align__(16) float sk[64];
    __shared__ float pd[128];
    __shared__ float od[128];
    __shared__ float s_scal[4];  // [0]=1/qsum, [1]=1/ksum, [2]=beta

    float W[32];
    #pragma unroll
    for (int i = 0; i < 32; i++) W[i] = 0.0f;

    // preload t=0
    {
        const float* p = qkvb + ((size_t)(0 * BSZ + b) * NPROJ) + h * 193;
        raw[0][tid] = p[tid];
        if (tid < 65) raw[0][128 + tid] = p[128 + tid];
    }
    __syncthreads();

    for (int t = 0; t < SLEN; t++) {
        const int cur = t & 1;
        const float* rawc = raw[cur];

        // issue prefetch for t+1 early
        float pf0 = 0.f, pf1 = 0.f;
        const bool has_next = (t + 1 < SLEN);
        if (has_next) {
            const float* pn = qkvb + ((size_t)((t + 1) * BSZ + b) * NPROJ) + h * 193;
            pf0 = pn[tid];
            if (tid < 65) pf1 = pn[128 + tid];
        }

        // activation: elu(x)+1 = x>0 ? x+1 : exp(x)
        {
            float xv = rawc[tid];
            float y = (xv > 0.f) ? (xv + 1.0f) : __expf(xv);
            if (tid < 64) sq[tid] = y;
            else          sk[tid - 64] = y;
        }
        __syncthreads();   // B: sq/sk ready

        // partial dot: W[r, j0:j0+32] . k_elu
        float pv0 = 0.f, pv1 = 0.f, pv2 = 0.f, pv3 = 0.f;
        #pragma unroll
        for (int j = 0; j < 32; j += 4) {
            float4 k4 = *(const float4*)&sk[j0 + j];
            pv0 = fmaf(W[j + 0], k4.x, pv0);
            pv1 = fmaf(W[j + 1], k4.y, pv1);
            pv2 = fmaf(W[j + 2], k4.z, pv2);
            pv3 = fmaf(W[j + 3], k4.w, pv3);
        }
        pd[tid] = (pv0 + pv1) + (pv2 + pv3);

        // reductions (warp 0: qsum, warp 1: ksum, warp 2: beta)
        if (wid == 0) {
            float s = sq[lane] + sq[lane + 32];
            #pragma unroll
            for (int o = 16; o > 0; o >>= 1) s += __shfl_xor_sync(0xffffffffu, s, o);
            if (lane == 0) s_scal[0] = 1.0f / s;
        } else if (wid == 1) {
            float s = sk[lane] + sk[lane + 32];
            #pragma unroll
            for (int o = 16; o > 0; o >>= 1) s += __shfl_xor_sync(0xffffffffu, s, o);
            if (lane == 0) s_scal[1] = 1.0f / s;
        } else if (wid == 2 && lane == 0) {
            float xb = rawc[192];
            s_scal[2] = 1.0f / (1.0f + __expf(-xb));
        }
        __syncthreads();   // C: pd + scalars ready

        float rki = s_scal[1];
        float vold = (pd[r] + pd[64 + r]) * rki;        // W . k_norm
        float vt = rawc[128 + r];
        float upd = s_scal[2] * (vt - vold) * rki;      // beta*(v - vold) * rk (fold norm)

        // W += upd * k_elu ; po = W_new . q_elu (partial)
        float po0 = 0.f, po1 = 0.f, po2 = 0.f, po3 = 0.f;
        #pragma unroll
        for (int j = 0; j < 32; j += 4) {
            float4 k4 = *(const float4*)&sk[j0 + j];
            float4 q4 = *(const float4*)&sq[j0 + j];
            W[j + 0] = fmaf(upd, k4.x, W[j + 0]);
            po0 = fmaf(W[j + 0], q4.x, po0);
            W[j + 1] = fmaf(upd, k4.y, W[j + 1]);
            po1 = fmaf(W[j + 1], q4.y, po1);
            W[j + 2] = fmaf(upd, k4.z, W[j + 2]);
            po2 = fmaf(W[j + 2], q4.z, po2);
            W[j + 3] = fmaf(upd, k4.w, W[j + 3]);
            po3 = fmaf(W[j + 3], q4.w, po3);
        }
        od[tid] = (po0 + po1) + (po2 + po3);

        // stage next step's raw
        if (has_next) {
            raw[cur ^ 1][tid] = pf0;
            if (tid < 65) raw[cur ^ 1][128 + tid] = pf1;
        }
        __syncthreads();   // D: od ready, next raw ready

        if (half == 0) {
            float o = (od[r] + od[64 + r]) * s_scal[0];   // * rq (fold norm)
            outs[((size_t)(t * BSZ + b) * INDIM) + h * HD + r] = o;
        }
    }
}

// ---------------- launch ----------------
extern "C" void kernel_launch(void* const* d_in, const int* in_sizes, int n_in,
                              void* d_out, int out_size) {
    const float* x      = (const float*)d_in[0];
    const float* gamma  = (const float*)d_in[1];
    const float* beta   = (const float*)d_in[2];
    const float* w_slow = (const float*)d_in[3];
    const float* w_out  = (const float*)d_in[4];
    float* out = (float*)d_out;

    float *h, *qkvb, *outs;
    cudaGetSymbolAddress((void**)&h, g_h);
    cudaGetSymbolAddress((void**)&qkvb, g_qkvb);
    cudaGetSymbolAddress((void**)&outs, g_outs);

    ln_kernel<<<NTOK, 128>>>(x, gamma, beta, h);

    dim3 g1((NPROJ + 127) / 128, NTOK / 128);
    sgemm_kernel<<<g1, 256>>>(h, w_slow, nullptr, qkvb, NTOK, NPROJ, INDIM);

    delta_kernel<<<BSZ * NH, 128>>>(qkvb, outs);

    dim3 g2(INDIM / 128, NTOK / 128);
    sgemm_kernel<<<g2, 256>>>(outs, w_out, x, out, NTOK, INDIM, NH * HD);
}

// round 2
// speedup vs baseline: 1.7514x; 1.7514x over previous
#include <cuda_runtime.h>
#include <cuda_bf16.h>
#include <cstdint>

// Problem dims (fixed by setup_inputs)
#define SLEN 1024
#define BSZ  32
#define INDIM 512
#define NH   8
#define HD   64
#define NTOK (SLEN*BSZ)          // 32768
#define NPROJ (NH*(3*HD+1))      // 1544
#define LN_EPS 1e-5f

// ---------------- scratch (device globals; no runtime alloc) ----------------
__device__ __align__(256) float g_qkvb[NTOK * NPROJ];            // projection output (fp32)
__device__ __align__(256) unsigned short g_hhi[NTOK * INDIM];    // LN output split
__device__ __align__(256) unsigned short g_hlo[NTOK * INDIM];
__device__ __align__(256) unsigned short g_ohi[NTOK * INDIM];    // recurrence out split
__device__ __align__(256) unsigned short g_olo[NTOK * INDIM];
__device__ __align__(256) unsigned short g_wshi[INDIM * NPROJ];  // w_slow split
__device__ __align__(256) unsigned short g_wslo[INDIM * NPROJ];
__device__ __align__(256) unsigned short g_wohi[INDIM * INDIM];  // w_out split
__device__ __align__(256) unsigned short g_wolo[INDIM * INDIM];

// ---------------- small helpers ----------------
__device__ __forceinline__ unsigned smem_u32(const void* p) {
    return (unsigned)__cvta_generic_to_shared(p);
}
__device__ __forceinline__ void cp16(unsigned dst, const void* src, int sz) {
    asm volatile("cp.async.cg.shared.global [%0], [%1], 16, %2;\n"
                 :: "r"(dst), "l"(src), "r"(sz));
}
__device__ __forceinline__ void cp_commit() {
    asm volatile("cp.async.commit_group;\n" ::: "memory");
}
__device__ __forceinline__ void ldm_x4(unsigned& r0, unsigned& r1, unsigned& r2, unsigned& r3, unsigned addr) {
    asm volatile("ldmatrix.sync.aligned.m8n8.x4.shared.b16 {%0,%1,%2,%3}, [%4];"
                 : "=r"(r0), "=r"(r1), "=r"(r2), "=r"(r3) : "r"(addr));
}
__device__ __forceinline__ void ldm_x4_t(unsigned& r0, unsigned& r1, unsigned& r2, unsigned& r3, unsigned addr) {
    asm volatile("ldmatrix.sync.aligned.m8n8.x4.trans.shared.b16 {%0,%1,%2,%3}, [%4];"
                 : "=r"(r0), "=r"(r1), "=r"(r2), "=r"(r3) : "r"(addr));
}
__device__ __forceinline__ void mma16816(float* d, const unsigned* a, unsigned b0, unsigned b1) {
    asm volatile("mma.sync.aligned.m16n8k16.row.col.f32.bf16.bf16.f32 "
                 "{%0,%1,%2,%3}, {%4,%5,%6,%7}, {%8,%9}, {%0,%1,%2,%3};"
                 : "+f"(d[0]), "+f"(d[1]), "+f"(d[2]), "+f"(d[3])
                 : "r"(a[0]), "r"(a[1]), "r"(a[2]), "r"(a[3]), "r"(b0), "r"(b1));
}
__device__ __forceinline__ unsigned short bf16_bits(__nv_bfloat16 v) {
    return *reinterpret_cast<unsigned short*>(&v);
}

// ---------------- LayerNorm (emits bf16 hi/lo split) ----------------
__global__ __launch_bounds__(128) void ln_kernel(const float* __restrict__ x,
                                                 const float* __restrict__ gamma,
                                                 const float* __restrict__ beta,
                                                 unsigned short* __restrict__ hhi,
                                                 unsigned short* __restrict__ hlo) {
    int row = blockIdx.x;
    int tid = threadIdx.x;
    int lane = tid & 31, wid = tid >> 5;
    const float4* xr = (const float4*)(x + (size_t)row * INDIM);
    float4 v = xr[tid];

    float s = v.x + v.y + v.z + v.w;
    #pragma unroll
    for (int o = 16; o > 0; o >>= 1) s += __shfl_xor_sync(0xffffffffu, s, o);
    __shared__ float sm[4], sm2[4];
    if (lane == 0) sm[wid] = s;
    __syncthreads();
    float mu = (sm[0] + sm[1] + sm[2] + sm[3]) * (1.0f / INDIM);

    float dx = v.x - mu, dy = v.y - mu, dz = v.z - mu, dw = v.w - mu;
    float sq = dx*dx + dy*dy + dz*dz + dw*dw;
    #pragma unroll
    for (int o = 16; o > 0; o >>= 1) sq += __shfl_xor_sync(0xffffffffu, sq, o);
    if (lane == 0) sm2[wid] = sq;
    __syncthreads();
    float var = (sm2[0] + sm2[1] + sm2[2] + sm2[3]) * (1.0f / INDIM);
    float rstd = rsqrtf(var + LN_EPS);

    float4 g = ((const float4*)gamma)[tid];
    float4 b = ((const float4*)beta)[tid];
    float o0 = dx * rstd * g.x + b.x;
    float o1 = dy * rstd * g.y + b.y;
    float o2 = dz * rstd * g.z + b.z;
    float o3 = dw * rstd * g.w + b.w;

    __nv_bfloat16 h0 = __float2bfloat16(o0), h1 = __float2bfloat16(o1);
    __nv_bfloat16 h2 = __float2bfloat16(o2), h3 = __float2bfloat16(o3);
    __nv_bfloat16 l0 = __float2bfloat16(o0 - __bfloat162float(h0));
    __nv_bfloat16 l1 = __float2bfloat16(o1 - __bfloat162float(h1));
    __nv_bfloat16 l2 = __float2bfloat16(o2 - __bfloat162float(h2));
    __nv_bfloat16 l3 = __float2bfloat16(o3 - __bfloat162float(h3));

    ushort4 hv; hv.x = bf16_bits(h0); hv.y = bf16_bits(h1); hv.z = bf16_bits(h2); hv.w = bf16_bits(h3);
    ushort4 lv; lv.x = bf16_bits(l0); lv.y = bf16_bits(l1); lv.z = bf16_bits(l2); lv.w = bf16_bits(l3);
    *(ushort4*)(hhi + (size_t)row * INDIM + 4 * tid) = hv;
    *(ushort4*)(hlo + (size_t)row * INDIM + 4 * tid) = lv;
}

// ---------------- weight split ----------------
__global__ void split_kernel(const float* __restrict__ w,
                             unsigned short* __restrict__ hi,
                             unsigned short* __restrict__ lo, int n) {
    int i = blockIdx.x * 256 + threadIdx.x;
    if (i < n) {
        float f = w[i];
        __nv_bfloat16 h = __float2bfloat16(f);
        __nv_bfloat16 l = __float2bfloat16(f - __bfloat162float(h));
        hi[i] = bf16_bits(h);
        lo[i] = bf16_bits(l);
    }
}

// ---------------- split-bf16 tensor-core GEMM ----------------
// C[M,N] = A@B (fp32 accum), A = Ahi+Alo (bf16), B = Bhi+Blo (bf16).
// Computes hi*hi + hi*lo + lo*hi (lo*lo negligible at 2^-16).
// Block tile 128x128, K-tile 16, 8 warps (4m x 2n), warp tile 32x64.
#define ASTG 12288   // bytes per A stage (2 parts x 128 x 24 bf16)
#define APART 6144
#define BSTG 8704    // bytes per B stage (2 parts x 16 x 136 bf16)
#define BPART 4352

__global__ __launch_bounds__(256) void gemm_split(const __nv_bfloat16* __restrict__ Ahi,
                                                  const __nv_bfloat16* __restrict__ Alo,
                                                  const __nv_bfloat16* __restrict__ Bhi,
                                                  const __nv_bfloat16* __restrict__ Blo,
                                                  const float* __restrict__ RES,
                                                  float* __restrict__ C,
                                                  int M, int N, int K) {
    __shared__ __align__(128) __nv_bfloat16 As[2][2][128 * 24];
    __shared__ __align__(128) __nv_bfloat16 Bs[2][2][16 * 136];

    const int tid = threadIdx.x, lane = tid & 31, wid = tid >> 5;
    const int m_blk = blockIdx.y * 128, n_blk = blockIdx.x * 128;
    const int wm = (wid & 3) * 32, wn = (wid >> 2) * 64;

    // cp.async source/dest mapping
    const int ar = tid >> 1, aseg = (tid & 1) * 8;   // A: 128 rows x 2 halves of 16B
    const int bk = tid >> 4, bseg = (tid & 15) * 8;  // B: 16 rows x 8 col-chunks
    const __nv_bfloat16* agh = Ahi + (size_t)(m_blk + ar) * K + aseg;
    const __nv_bfloat16* agl = Alo + (size_t)(m_blk + ar) * K + aseg;
    const __nv_bfloat16* bgh = Bhi + (size_t)bk * N + n_blk + bseg;
    const __nv_bfloat16* bgl = Blo + (size_t)bk * N + n_blk + bseg;
    const int bsz = (n_blk + bseg + 8 <= N) ? 16 : 0;

    const unsigned aS = smem_u32(&As[0][0][0]);
    const unsigned bS = smem_u32(&Bs[0][0][0]);
    const unsigned adst = aS + (ar * 24 + aseg) * 2;
    const unsigned bdst = bS + (bk * 136 + bseg) * 2;

#define GISSUE(T, ST) do { \
    cp16(adst + (ST) * ASTG,          agh + (T) * 16, 16); \
    cp16(adst + (ST) * ASTG + APART,  agl + (T) * 16, 16); \
    cp16(bdst + (ST) * BSTG,          bgh + (size_t)(T) * 16 * N, bsz); \
    cp16(bdst + (ST) * BSTG + BPART,  bgl + (size_t)(T) * 16 * N, bsz); \
    cp_commit(); } while (0)

    // ldmatrix per-thread base addresses
    const int arow = lane & 15;
    const unsigned aLd = aS + ((wm + arow) * 24 + ((lane >> 4) * 8)) * 2;
    const unsigned bLd = bS + ((lane & 15) * 136 + wn + ((lane >> 4) * 8)) * 2;

    float acc[2][8][4];
    #pragma unroll
    for (int i = 0; i < 2; i++)
        #pragma unroll
        for (int j = 0; j < 8; j++)
            #pragma unroll
            for (int q = 0; q < 4; q++) acc[i][j][q] = 0.0f;

    GISSUE(0, 0);
    GISSUE(1, 1);
    const int NT = K / 16;

    for (int t = 0; t < NT; t++) {
        if (t < NT - 1) asm volatile("cp.async.wait_group 1;\n" ::: "memory");
        else            asm volatile("cp.async.wait_group 0;\n" ::: "memory");
        __syncthreads();

        const int st = t & 1;
        const unsigned aOf = aLd + st * ASTG;
        const unsigned bOf = bLd + st * BSTG;

        unsigned ahi[2][4], bhi[4][4], tmp[4];
        #pragma unroll
        for (int mf = 0; mf < 2; mf++)
            ldm_x4(ahi[mf][0], ahi[mf][1], ahi[mf][2], ahi[mf][3], aOf + mf * 768);
        #pragma unroll
        for (int g = 0; g < 4; g++)
            ldm_x4_t(bhi[g][0], bhi[g][1], bhi[g][2], bhi[g][3], bOf + g * 32);

        // hi * hi
        #pragma unroll
        for (int mf = 0; mf < 2; mf++)
            #pragma unroll
            for (int nf = 0; nf < 8; nf++)
                mma16816(acc[mf][nf], ahi[mf], bhi[nf >> 1][(nf & 1) * 2], bhi[nf >> 1][(nf & 1) * 2 + 1]);
        // lo * hi
        #pragma unroll
        for (int mf = 0; mf < 2; mf++) {
            ldm_x4(tmp[0], tmp[1], tmp[2], tmp[3], aOf + APART + mf * 768);
            #pragma unroll
            for (int nf = 0; nf < 8; nf++)
                mma16816(acc[mf][nf], tmp, bhi[nf >> 1][(nf & 1) * 2], bhi[nf >> 1][(nf & 1) * 2 + 1]);
        }
        // hi * lo
        #pragma unroll
        for (int g = 0; g < 4; g++) {
            ldm_x4_t(tmp[0], tmp[1], tmp[2], tmp[3], bOf + BPART + g * 32);
            #pragma unroll
            for (int mf = 0; mf < 2; mf++) {
                mma16816(acc[mf][2 * g],     ahi[mf], tmp[0], tmp[1]);
                mma16816(acc[mf][2 * g + 1], ahi[mf], tmp[2], tmp[3]);
            }
        }
        __syncthreads();
        if (t + 2 < NT) GISSUE(t + 2, st);
    }

    // epilogue
    #pragma unroll
    for (int mf = 0; mf < 2; mf++) {
        int row = m_blk + wm + mf * 16 + (lane >> 2);
        #pragma unroll
        for (int nf = 0; nf < 8; nf++) {
            int col = n_blk + wn + nf * 8 + (lane & 3) * 2;
            if (col < N) {
                float2 v0 = make_float2(acc[mf][nf][0], acc[mf][nf][1]);
                float2 v1 = make_float2(acc[mf][nf][2], acc[mf][nf][3]);
                if (RES) {
                    float2 r0 = *(const float2*)(RES + (size_t)row * N + col);
                    float2 r1 = *(const float2*)(RES + (size_t)(row + 8) * N + col);
                    v0.x += r0.x; v0.y += r0.y; v1.x += r1.x; v1.y += r1.y;
                }
                *(float2*)(C + (size_t)row * N + col) = v0;
                *(float2*)(C + (size_t)(row + 8) * N + col) = v1;
            }
        }
    }
#undef GISSUE
}

// ---------------- Delta-rule recurrence ----------------
// 2 heads per CTA (grid 128, single wave). Per head: 128 threads (4 warps).
// Thread layout: warp wl owns rows wl*16..wl*16+15; lane&15 = row offset,
// lane>>4 = column half (0:[0,32) 1:[32,64)). W half-row in regs (32 floats).
// Half-row combines via shfl_xor(16). One __syncthreads per step.
__global__ __launch_bounds__(256) void delta_kernel(const float* __restrict__ qkvb,
                                                    unsigned short* __restrict__ ohi,
                                                    unsigned short* __restrict__ olo) {
    const int tid = threadIdx.x;
    const int hl = tid >> 7;             // head within CTA
    const int ht = tid & 127;
    const int lane = tid & 31;
    const int wl = ht >> 5;              // warp within head
    const int bh = blockIdx.x * 2 + hl;  // 0..255
    const int b = bh >> 3, h = bh & 7;
    const int r = wl * 16 + (lane & 15);
    const int hf = lane >> 4;

    __shared__ float sq[2][2][64];       // [head][parity][dim]
    __shared__ float sk[2][2][64];

    const float* base = qkvb + (size_t)b * NPROJ + h * 193;
    const size_t tstr = (size_t)BSZ * NPROJ;

    float W[32];
    #pragma unroll
    for (int i = 0; i < 32; i++) W[i] = 0.0f;

    // distance-2 prefetch pipeline
    float cqk = base[ht], cv = base[128 + r], cb = base[192];
    float nqk = base[tstr + ht], nv = base[tstr + 128 + r], nb = base[tstr + 192];

    for (int t = 0; t < SLEN; t++) {
        float mqk = 0.f, mv = 0.f, mb = 0.f;
        if (t + 2 < SLEN) {
            const float* p = base + tstr * (t + 2);
            mqk = p[ht]; mv = p[128 + r]; mb = p[192];
        }

        const int cur = t & 1;
        // elu(x)+1
        float y = (cqk > 0.f) ? (cqk + 1.0f) : __expf(cqk);
        if (ht < 64) sq[hl][cur][ht] = y;
        else         sk[hl][cur][ht - 64] = y;
        __syncthreads();

        // per-warp redundant reductions
        float s1 = sq[hl][cur][lane] + sq[hl][cur][lane + 32];
        float s2 = sk[hl][cur][lane] + sk[hl][cur][lane + 32];
        #pragma unroll
        for (int o = 16; o > 0; o >>= 1) {
            s1 += __shfl_xor_sync(0xffffffffu, s1, o);
            s2 += __shfl_xor_sync(0xffffffffu, s2, o);
        }
        float rq = 1.0f / s1;
        float rk = 1.0f / s2;
        float bsig = 1.0f / (1.0f + __expf(-cb));

        // load k half-vector, partial dot W.k
        float kreg[32];
        float pv0 = 0.f, pv1 = 0.f, pv2 = 0.f, pv3 = 0.f;
        #pragma unroll
        for (int j = 0; j < 8; j++) {
            float4 k4 = *(const float4*)&sk[hl][cur][hf * 32 + j * 4];
            kreg[j*4+0] = k4.x; kreg[j*4+1] = k4.y; kreg[j*4+2] = k4.z; kreg[j*4+3] = k4.w;
            pv0 = fmaf(W[j*4+0], k4.x, pv0);
            pv1 = fmaf(W[j*4+1], k4.y, pv1);
            pv2 = fmaf(W[j*4+2], k4.z, pv2);
            pv3 = fmaf(W[j*4+3], k4.w, pv3);
        }
        float pv = (pv0 + pv1) + (pv2 + pv3);
        pv += __shfl_xor_sync(0xffffffffu, pv, 16);
        float vold = pv * rk;
        float upd = bsig * (cv - vold) * rk;

        // W += upd*k ; po = W_new . q
        float po0 = 0.f, po1 = 0.f, po2 = 0.f, po3 = 0.f;
        #pragma unroll
        for (int j = 0; j < 8; j++) {
            float4 q4 = *(const float4*)&sq[hl][cur][hf * 32 + j * 4];
            W[j*4+0] = fmaf(upd, kreg[j*4+0], W[j*4+0]);
            po0 = fmaf(W[j*4+0], q4.x, po0);
            W[j*4+1] = fmaf(upd, kreg[j*4+1], W[j*4+1]);
            po1 = fmaf(W[j*4+1], q4.y, po1);
            W[j*4+2] = fmaf(upd, kreg[j*4+2], W[j*4+2]);
            po2 = fmaf(W[j*4+2], q4.z, po2);
            W[j*4+3] = fmaf(upd, kreg[j*4+3], W[j*4+3]);
            po3 = fmaf(W[j*4+3], q4.w, po3);
        }
        float po = (po0 + po1) + (po2 + po3);
        po += __shfl_xor_sync(0xffffffffu, po, 16);
        float o = po * rq;

        if (lane < 16) {
            size_t oi = ((size_t)t * BSZ + b) * (size_t)INDIM + h * HD + r;
            __nv_bfloat16 oh = __float2bfloat16(o);
            __nv_bfloat16 ol = __float2bfloat16(o - __bfloat162float(oh));
            ohi[oi] = bf16_bits(oh);
            olo[oi] = bf16_bits(ol);
        }

        cqk = nqk; cv = nv; cb = nb;
        nqk = mqk; nv = mv; nb = mb;
    }
}

// ---------------- launch ----------------
extern "C" void kernel_launch(void* const* d_in, const int* in_sizes, int n_in,
                              void* d_out, int out_size) {
    const float* x      = (const float*)d_in[0];
    const float* gamma  = (const float*)d_in[1];
    const float* beta   = (const float*)d_in[2];
    const float* w_slow = (const float*)d_in[3];
    const float* w_out  = (const float*)d_in[4];
    float* out = (float*)d_out;

    float* qkvb;
    unsigned short *hhi, *hlo, *ohi, *olo, *wshi, *wslo, *wohi, *wolo;
    cudaGetSymbolAddress((void**)&qkvb, g_qkvb);
    cudaGetSymbolAddress((void**)&hhi, g_hhi);
    cudaGetSymbolAddress((void**)&hlo, g_hlo);
    cudaGetSymbolAddress((void**)&ohi, g_ohi);
    cudaGetSymbolAddress((void**)&olo, g_olo);
    cudaGetSymbolAddress((void**)&wshi, g_wshi);
    cudaGetSymbolAddress((void**)&wslo, g_wslo);
    cudaGetSymbolAddress((void**)&wohi, g_wohi);
    cudaGetSymbolAddress((void**)&wolo, g_wolo);

    ln_kernel<<<NTOK, 128>>>(x, gamma, beta, hhi, hlo);
    split_kernel<<<(INDIM * NPROJ + 255) / 256, 256>>>(w_slow, wshi, wslo, INDIM * NPROJ);
    split_kernel<<<(INDIM * INDIM + 255) / 256, 256>>>(w_out, wohi, wolo, INDIM * INDIM);

    dim3 g1((NPROJ + 127) / 128, NTOK / 128);
    gemm_split<<<g1, 256>>>((const __nv_bfloat16*)hhi, (const __nv_bfloat16*)hlo,
                            (const __nv_bfloat16*)wshi, (const __nv_bfloat16*)wslo,
                            nullptr, qkvb, NTOK, NPROJ, INDIM);

    delta_kernel<<<BSZ * NH / 2, 256>>>(qkvb, ohi, olo);

    dim3 g2(INDIM / 128, NTOK / 128);
    gemm_split<<<g2, 256>>>((const __nv_bfloat16*)ohi, (const __nv_bfloat16*)olo,
                            (const __nv_bfloat16*)wohi, (const __nv_bfloat16*)wolo,
                            x, out, NTOK, INDIM, NH * HD);
}

// round 4
// speedup vs baseline: 1.8108x; 1.0339x over previous
#include <cuda_runtime.h>
#include <cuda_bf16.h>
#include <cstdint>

// Problem dims (fixed by setup_inputs)
#define SLEN 1024
#define BSZ  32
#define INDIM 512
#define NH   8
#define HD   64
#define NTOK (SLEN*BSZ)          // 32768
#define NPROJ (NH*(3*HD+1))      // 1544
#define LN_EPS 1e-5f

// ---------------- scratch (device globals; no runtime alloc) ----------------
__device__ __align__(256) float g_qkvb[NTOK * NPROJ];            // projection output (fp32)
__device__ __align__(256) unsigned short g_hhi[NTOK * INDIM];    // LN output split
__device__ __align__(256) unsigned short g_hlo[NTOK * INDIM];
__device__ __align__(256) unsigned short g_ohi[NTOK * INDIM];    // recurrence out split
__device__ __align__(256) unsigned short g_olo[NTOK * INDIM];
__device__ __align__(256) unsigned short g_wshi[INDIM * NPROJ];  // w_slow split
__device__ __align__(256) unsigned short g_wslo[INDIM * NPROJ];
__device__ __align__(256) unsigned short g_wohi[INDIM * INDIM];  // w_out split
__device__ __align__(256) unsigned short g_wolo[INDIM * INDIM];

// ---------------- small helpers ----------------
__device__ __forceinline__ unsigned smem_u32(const void* p) {
    return (unsigned)__cvta_generic_to_shared(p);
}
__device__ __forceinline__ void cp16(unsigned dst, const void* src, int sz) {
    asm volatile("cp.async.cg.shared.global [%0], [%1], 16, %2;\n"
                 :: "r"(dst), "l"(src), "r"(sz));
}
__device__ __forceinline__ void cp_commit() {
    asm volatile("cp.async.commit_group;\n" ::: "memory");
}
__device__ __forceinline__ void ldm_x4(unsigned& r0, unsigned& r1, unsigned& r2, unsigned& r3, unsigned addr) {
    asm volatile("ldmatrix.sync.aligned.m8n8.x4.shared.b16 {%0,%1,%2,%3}, [%4];"
                 : "=r"(r0), "=r"(r1), "=r"(r2), "=r"(r3) : "r"(addr));
}
__device__ __forceinline__ void ldm_x4_t(unsigned& r0, unsigned& r1, unsigned& r2, unsigned& r3, unsigned addr) {
    asm volatile("ldmatrix.sync.aligned.m8n8.x4.trans.shared.b16 {%0,%1,%2,%3}, [%4];"
                 : "=r"(r0), "=r"(r1), "=r"(r2), "=r"(r3) : "r"(addr));
}
__device__ __forceinline__ void mma16816(float* d, const unsigned* a, unsigned b0, unsigned b1) {
    asm volatile("mma.sync.aligned.m16n8k16.row.col.f32.bf16.bf16.f32 "
                 "{%0,%1,%2,%3}, {%4,%5,%6,%7}, {%8,%9}, {%0,%1,%2,%3};"
                 : "+f"(d[0]), "+f"(d[1]), "+f"(d[2]), "+f"(d[3])
                 : "r"(a[0]), "r"(a[1]), "r"(a[2]), "r"(a[3]), "r"(b0), "r"(b1));
}
__device__ __forceinline__ unsigned short bf16_bits(__nv_bfloat16 v) {
    return *reinterpret_cast<unsigned short*>(&v);
}

// ---------------- LayerNorm (emits bf16 hi/lo split) ----------------
__global__ __launch_bounds__(128) void ln_kernel(const float* __restrict__ x,
                                                 const float* __restrict__ gamma,
                                                 const float* __restrict__ beta,
                                                 unsigned short* __restrict__ hhi,
                                                 unsigned short* __restrict__ hlo) {
    int row = blockIdx.x;
    int tid = threadIdx.x;
    int lane = tid & 31, wid = tid >> 5;
    const float4* xr = (const float4*)(x + (size_t)row * INDIM);
    float4 v = xr[tid];

    float s = v.x + v.y + v.z + v.w;
    #pragma unroll
    for (int o = 16; o > 0; o >>= 1) s += __shfl_xor_sync(0xffffffffu, s, o);
    __shared__ float sm[4], sm2[4];
    if (lane == 0) sm[wid] = s;
    __syncthreads();
    float mu = (sm[0] + sm[1] + sm[2] + sm[3]) * (1.0f / INDIM);

    float dx = v.x - mu, dy = v.y - mu, dz = v.z - mu, dw = v.w - mu;
    float sq = dx*dx + dy*dy + dz*dz + dw*dw;
    #pragma unroll
    for (int o = 16; o > 0; o >>= 1) sq += __shfl_xor_sync(0xffffffffu, sq, o);
    if (lane == 0) sm2[wid] = sq;
    __syncthreads();
    float var = (sm2[0] + sm2[1] + sm2[2] + sm2[3]) * (1.0f / INDIM);
    float rstd = rsqrtf(var + LN_EPS);

    float4 g = ((const float4*)gamma)[tid];
    float4 b = ((const float4*)beta)[tid];
    float o0 = dx * rstd * g.x + b.x;
    float o1 = dy * rstd * g.y + b.y;
    float o2 = dz * rstd * g.z + b.z;
    float o3 = dw * rstd * g.w + b.w;

    __nv_bfloat16 h0 = __float2bfloat16(o0), h1 = __float2bfloat16(o1);
    __nv_bfloat16 h2 = __float2bfloat16(o2), h3 = __float2bfloat16(o3);
    __nv_bfloat16 l0 = __float2bfloat16(o0 - __bfloat162float(h0));
    __nv_bfloat16 l1 = __float2bfloat16(o1 - __bfloat162float(h1));
    __nv_bfloat16 l2 = __float2bfloat16(o2 - __bfloat162float(h2));
    __nv_bfloat16 l3 = __float2bfloat16(o3 - __bfloat162float(h3));

    ushort4 hv; hv.x = bf16_bits(h0); hv.y = bf16_bits(h1); hv.z = bf16_bits(h2); hv.w = bf16_bits(h3);
    ushort4 lv; lv.x = bf16_bits(l0); lv.y = bf16_bits(l1); lv.z = bf16_bits(l2); lv.w = bf16_bits(l3);
    *(ushort4*)(hhi + (size_t)row * INDIM + 4 * tid) = hv;
    *(ushort4*)(hlo + (size_t)row * INDIM + 4 * tid) = lv;
}

// ---------------- weight split ----------------
__global__ void split_kernel(const float* __restrict__ w,
                             unsigned short* __restrict__ hi,
                             unsigned short* __restrict__ lo, int n) {
    int i = blockIdx.x * 256 + threadIdx.x;
    if (i < n) {
        float f = w[i];
        __nv_bfloat16 h = __float2bfloat16(f);
        __nv_bfloat16 l = __float2bfloat16(f - __bfloat162float(h));
        hi[i] = bf16_bits(h);
        lo[i] = bf16_bits(l);
    }
}

// ---------------- split-bf16 tensor-core GEMM (3-stage pipeline) ----------------
// C[M,N] = A@B (fp32 accum), A = Ahi+Alo (bf16), B = Bhi+Blo (bf16).
// Computes hi*hi + hi*lo + lo*hi. Block tile 128x128, K-tile 16, 8 warps.
// Per-stage layout: [Ahi 6144B | Alo 6144B | Bhi 4352B | Blo 4352B] = 20992B, 3 stages.
#define STG   20992
#define A_LO  6144
#define B_HI  12288
#define B_P   4352
#define SMEM_GEMM (3 * STG)

__global__ __launch_bounds__(256) void gemm_split(const __nv_bfloat16* __restrict__ Ahi,
                                                  const __nv_bfloat16* __restrict__ Alo,
                                                  const __nv_bfloat16* __restrict__ Bhi,
                                                  const __nv_bfloat16* __restrict__ Blo,
                                                  const float* __restrict__ RES,
                                                  float* __restrict__ C,
                                                  int M, int N, int K) {
    extern __shared__ __align__(128) char dsm[];

    const int tid = threadIdx.x, lane = tid & 31, wid = tid >> 5;
    const int m_blk = blockIdx.y * 128, n_blk = blockIdx.x * 128;
    const int wm = (wid & 3) * 32, wn = (wid >> 2) * 64;

    // cp.async source/dest mapping
    const int ar = tid >> 1, aseg = (tid & 1) * 8;   // A: 128 rows x 2 halves of 16B
    const int bk = tid >> 4, bseg = (tid & 15) * 8;  // B: 16 rows x 8 col-chunks
    const __nv_bfloat16* agh = Ahi + (size_t)(m_blk + ar) * K + aseg;
    const __nv_bfloat16* agl = Alo + (size_t)(m_blk + ar) * K + aseg;
    const __nv_bfloat16* bgh = Bhi + (size_t)bk * N + n_blk + bseg;
    const __nv_bfloat16* bgl = Blo + (size_t)bk * N + n_blk + bseg;
    const int bsz = (n_blk + bseg + 8 <= N) ? 16 : 0;

    const unsigned sb = smem_u32(dsm);
    const unsigned adst = sb + (ar * 24 + aseg) * 2;
    const unsigned bdst = sb + B_HI + (bk * 136 + bseg) * 2;

#define GISSUE(T, ST) do { \
    unsigned off_ = (unsigned)(ST) * STG; \
    cp16(adst + off_,         agh + (T) * 16, 16); \
    cp16(adst + off_ + A_LO,  agl + (T) * 16, 16); \
    cp16(bdst + off_,         bgh + (size_t)(T) * 16 * N, bsz); \
    cp16(bdst + off_ + B_P,   bgl + (size_t)(T) * 16 * N, bsz); \
    cp_commit(); } while (0)

    // ldmatrix per-thread base addresses
    const int arow = lane & 15;
    const unsigned aLd = sb + ((wm + arow) * 24 + ((lane >> 4) * 8)) * 2;
    const unsigned bLd = sb + B_HI + ((lane & 15) * 136 + wn + ((lane >> 4) * 8)) * 2;

    float acc[2][8][4];
    #pragma unroll
    for (int i = 0; i < 2; i++)
        #pragma unroll
        for (int j = 0; j < 8; j++)
            #pragma unroll
            for (int q = 0; q < 4; q++) acc[i][j][q] = 0.0f;

    const int NT = K / 16;
    GISSUE(0, 0);
    GISSUE(1, 1);

    int st = 0, st2 = 2;
    for (int t = 0; t < NT; t++) {
        if (t < NT - 1) asm volatile("cp.async.wait_group 1;\n" ::: "memory");
        else            asm volatile("cp.async.wait_group 0;\n" ::: "memory");
        __syncthreads();

        if (t + 2 < NT) GISSUE(t + 2, st2);

        const unsigned aOf = aLd + st * STG;
        const unsigned bOf = bLd + st * STG;

        unsigned ahi[2][4], bhi[4][4], tmp[4];
        #pragma unroll
        for (int mf = 0; mf < 2; mf++)
            ldm_x4(ahi[mf][0], ahi[mf][1], ahi[mf][2], ahi[mf][3], aOf + mf * 768);
        #pragma unroll
        for (int g = 0; g < 4; g++)
            ldm_x4_t(bhi[g][0], bhi[g][1], bhi[g][2], bhi[g][3], bOf + g * 32);

        // hi * hi
        #pragma unroll
        for (int mf = 0; mf < 2; mf++)
            #pragma unroll
            for (int nf = 0; nf < 8; nf++)
                mma16816(acc[mf][nf], ahi[mf], bhi[nf >> 1][(nf & 1) * 2], bhi[nf >> 1][(nf & 1) * 2 + 1]);
        // lo * hi
        #pragma unroll
        for (int mf = 0; mf < 2; mf++) {
            ldm_x4(tmp[0], tmp[1], tmp[2], tmp[3], aOf + A_LO + mf * 768);
            #pragma unroll
            for (int nf = 0; nf < 8; nf++)
                mma16816(acc[mf][nf], tmp, bhi[nf >> 1][(nf & 1) * 2], bhi[nf >> 1][(nf & 1) * 2 + 1]);
        }
        // hi * lo
        #pragma unroll
        for (int g = 0; g < 4; g++) {
            ldm_x4_t(tmp[0], tmp[1], tmp[2], tmp[3], bOf + B_P + g * 32);
            #pragma unroll
            for (int mf = 0; mf < 2; mf++) {
                mma16816(acc[mf][2 * g],     ahi[mf], tmp[0], tmp[1]);
                mma16816(acc[mf][2 * g + 1], ahi[mf], tmp[2], tmp[3]);
            }
        }

        st = (st == 2) ? 0 : st + 1;
        st2 = (st2 == 2) ? 0 : st2 + 1;
    }

    // epilogue
    #pragma unroll
    for (int mf = 0; mf < 2; mf++) {
        int row = m_blk + wm + mf * 16 + (lane >> 2);
        #pragma unroll
        for (int nf = 0; nf < 8; nf++) {
            int col = n_blk + wn + nf * 8 + (lane & 3) * 2;
            if (col < N) {
                float2 v0 = make_float2(acc[mf][nf][0], acc[mf][nf][1]);
                float2 v1 = make_float2(acc[mf][nf][2], acc[mf][nf][3]);
                if (RES) {
                    float2 r0 = *(const float2*)(RES + (size_t)row * N + col);
                    float2 r1 = *(const float2*)(RES + (size_t)(row + 8) * N + col);
                    v0.x += r0.x; v0.y += r0.y; v1.x += r1.x; v1.y += r1.y;
                }
                *(float2*)(C + (size_t)row * N + col) = v0;
                *(float2*)(C + (size_t)(row + 8) * N + col) = v1;
            }
        }
    }
#undef GISSUE
}

// ---------------- Delta-rule recurrence ----------------
// 2 heads per CTA (grid 128, single wave), 512 threads (8 warps per head).
// Quarter-row decomposition: warp w8 owns rows w8*8..w8*8+7; within a warp,
// lane = seg*8 + rlow: thread owns W[r][seg*16 .. seg*16+16) in 16 registers.
// Segment combines are shfl_xor(8) + shfl_xor(16) (both flip seg bits only).
// Per-head named barrier; one barrier per step; double-buffered q/k smem.
__global__ __launch_bounds__(512) void delta_kernel(const float* __restrict__ qkvb,
                                                    unsigned short* __restrict__ ohi,
                                                    unsigned short* __restrict__ olo) {
    const int tid = threadIdx.x;
    const int hl = tid >> 8;             // head within CTA (0/1)
    const int ht = tid & 255;
    const int lane = tid & 31;
    const int w8 = ht >> 5;              // warp within head (0..7)
    const int r = w8 * 8 + (lane & 7);   // W row (0..63)
    const int seg = lane >> 3;           // column segment (0..3)
    const int j0 = seg * 16;
    const int bh = blockIdx.x * 2 + hl;  // 0..255
    const int b = bh >> 3, h = bh & 7;

    __shared__ float sq[2][2][64];       // [head][parity][dim]
    __shared__ float sk[2][2][64];

    const float* base = qkvb + (size_t)b * NPROJ + h * 193;
    const size_t tstr = (size_t)BSZ * NPROJ;

    float W[16];
    #pragma unroll
    for (int i = 0; i < 16; i++) W[i] = 0.0f;

    // distance-2 prefetch pipeline
    float cqk = 0.f, nqk = 0.f;
    if (ht < 128) { cqk = base[ht]; nqk = base[tstr + ht]; }
    float cv = base[128 + r], nv = base[tstr + 128 + r];
    float cb = base[192],     nb = base[tstr + 192];

    for (int t = 0; t < SLEN; t++) {
        float mqk = 0.f, mv = 0.f, mb = 0.f;
        if (t + 2 < SLEN) {
            const float* p = base + tstr * (t + 2);
            if (ht < 128) mqk = p[ht];
            mv = p[128 + r]; mb = p[192];
        }

        const int cur = t & 1;
        if (ht < 128) {
            float y = (cqk > 0.f) ? (cqk + 1.0f) : __expf(cqk);
            if (ht < 64) sq[hl][cur][ht] = y;
            else         sk[hl][cur][ht - 64] = y;
        }
        asm volatile("bar.sync %0, 256;" :: "r"(hl + 1) : "memory");

        // per-warp redundant sum reductions for sum_norm
        float s1 = sq[hl][cur][lane] + sq[hl][cur][lane + 32];
        float s2 = sk[hl][cur][lane] + sk[hl][cur][lane + 32];
        #pragma unroll
        for (int o = 16; o > 0; o >>= 1) {
            s1 += __shfl_xor_sync(0xffffffffu, s1, o);
            s2 += __shfl_xor_sync(0xffffffffu, s2, o);
        }
        float rq = 1.0f / s1;
        float rk = 1.0f / s2;
        float bsig = 1.0f / (1.0f + __expf(-cb));

        // partial dot W[r, j0:j0+16) . k
        float kreg[16];
        float pv0 = 0.f, pv1 = 0.f, pv2 = 0.f, pv3 = 0.f;
        #pragma unroll
        for (int j = 0; j < 4; j++) {
            float4 k4 = *(const float4*)&sk[hl][cur][j0 + j * 4];
            kreg[j*4+0] = k4.x; kreg[j*4+1] = k4.y; kreg[j*4+2] = k4.z; kreg[j*4+3] = k4.w;
            pv0 = fmaf(W[j*4+0], k4.x, pv0);
            pv1 = fmaf(W[j*4+1], k4.y, pv1);
            pv2 = fmaf(W[j*4+2], k4.z, pv2);
            pv3 = fmaf(W[j*4+3], k4.w, pv3);
        }
        float pv = (pv0 + pv1) + (pv2 + pv3);
        pv += __shfl_xor_sync(0xffffffffu, pv, 8);
        pv += __shfl_xor_sync(0xffffffffu, pv, 16);
        float upd = bsig * (cv - pv * rk) * rk;

        // W += upd*k ; po = W_new . q (partial)
        float po0 = 0.f, po1 = 0.f, po2 = 0.f, po3 = 0.f;
        #pragma unroll
        for (int j = 0; j < 4; j++) {
            float4 q4 = *(const float4*)&sq[hl][cur][j0 + j * 4];
            W[j*4+0] = fmaf(upd, kreg[j*4+0], W[j*4+0]);
            po0 = fmaf(W[j*4+0], q4.x, po0);
            W[j*4+1] = fmaf(upd, kreg[j*4+1], W[j*4+1]);
            po1 = fmaf(W[j*4+1], q4.y, po1);
            W[j*4+2] = fmaf(upd, kreg[j*4+2], W[j*4+2]);
            po2 = fmaf(W[j*4+2], q4.z, po2);
            W[j*4+3] = fmaf(upd, kreg[j*4+3], W[j*4+3]);
            po3 = fmaf(W[j*4+3], q4.w, po3);
        }
        float po = (po0 + po1) + (po2 + po3);
        po += __shfl_xor_sync(0xffffffffu, po, 8);
        po += __shfl_xor_sync(0xffffffffu, po, 16);
        float o = po * rq;

        if (seg == 0) {
            size_t oi = ((size_t)t * BSZ + b) * (size_t)INDIM + h * HD + r;
            __nv_bfloat16 oh = __float2bfloat16(o);
            __nv_bfloat16 ol = __float2bfloat16(o - __bfloat162float(oh));
            ohi[oi] = bf16_bits(oh);
            olo[oi] = bf16_bits(ol);
        }

        cqk = nqk; cv = nv; cb = nb;
        nqk = mqk; nv = mv; nb = mb;
    }
}

// ---------------- launch ----------------
extern "C" void kernel_launch(void* const* d_in, const int* in_sizes, int n_in,
                              void* d_out, int out_size) {
    const float* x      = (const float*)d_in[0];
    const float* gamma  = (const float*)d_in[1];
    const float* beta   = (const float*)d_in[2];
    const float* w_slow = (const float*)d_in[3];
    const float* w_out  = (const float*)d_in[4];
    float* out = (float*)d_out;

    float* qkvb;
    unsigned short *hhi, *hlo, *ohi, *olo, *wshi, *wslo, *wohi, *wolo;
    cudaGetSymbolAddress((void**)&qkvb, g_qkvb);
    cudaGetSymbolAddress((void**)&hhi, g_hhi);
    cudaGetSymbolAddress((void**)&hlo, g_hlo);
    cudaGetSymbolAddress((void**)&ohi, g_ohi);
    cudaGetSymbolAddress((void**)&olo, g_olo);
    cudaGetSymbolAddress((void**)&wshi, g_wshi);
    cudaGetSymbolAddress((void**)&wslo, g_wslo);
    cudaGetSymbolAddress((void**)&wohi, g_wohi);
    cudaGetSymbolAddress((void**)&wolo, g_wolo);

    // Idempotent, host-side, not stream-ordered: safe under graph capture,
    // and unconditional (no static guards per harness rules).
    cudaFuncSetAttribute(gemm_split, cudaFuncAttributeMaxDynamicSharedMemorySize, SMEM_GEMM);

    ln_kernel<<<NTOK, 128>>>(x, gamma, beta, hhi, hlo);
    split_kernel<<<(INDIM * NPROJ + 255) / 256, 256>>>(w_slow, wshi, wslo, INDIM * NPROJ);
    split_kernel<<<(INDIM * INDIM + 255) / 256, 256>>>(w_out, wohi, wolo, INDIM * INDIM);

    dim3 g1((NPROJ + 127) / 128, NTOK / 128);
    gemm_split<<<g1, 256, SMEM_GEMM>>>((const __nv_bfloat16*)hhi, (const __nv_bfloat16*)hlo,
                                       (const __nv_bfloat16*)wshi, (const __nv_bfloat16*)wslo,
                                       nullptr, qkvb, NTOK, NPROJ, INDIM);

    delta_kernel<<<BSZ * NH / 2, 512>>>(qkvb, ohi, olo);

    dim3 g2(INDIM / 128, NTOK / 128);
    gemm_split<<<g2, 256, SMEM_GEMM>>>((const __nv_bfloat16*)ohi, (const __nv_bfloat16*)olo,
                                       (const __nv_bfloat16*)wohi, (const __nv_bfloat16*)wolo,
                                       x, out, NTOK, INDIM, NH * HD);
}